// round 11
// baseline (speedup 1.0000x reference)
#include <cuda_runtime.h>
#include <cuda_fp16.h>
#include <math.h>
#include <cstdint>

// Problem constants
#define BSZ 2
#define TSEQ 2048
#define DM   1024
#define HN   16
#define HDM  64
#define MTOT (BSZ*TSEQ)   // 4096

// Scratch (allocation-free rule: __device__ globals)
__device__ __half g_x16 [MTOT*DM];
__device__ __half g_wq16[DM*DM];
__device__ __half g_wk16[DM*DM];
__device__ __half g_wv16[DM*DM];
__device__ __half g_wo16[DM*DM];
__device__ __half g_Q16 [BSZ*HN*TSEQ*HDM];  // [B,H,T,hd], pre-scaled 1/8
__device__ __half g_K16 [BSZ*HN*TSEQ*HDM];  // [B,H,T,hd]
__device__ __half g_Vt16[BSZ*HN*HDM*TSEQ];  // [B,H,hd,T]
__device__ __half g_O16 [MTOT*DM];          // [B*T, D]

// ---------------------------------------------------------------------------
// helpers
// ---------------------------------------------------------------------------
__device__ __forceinline__ uint32_t pk(float lo, float hi) {
    __half2 h = __floats2half2_rn(lo, hi);
    return *(uint32_t*)&h;
}
__device__ __forceinline__ uint32_t smem_u32(const void* p) {
    uint32_t a;
    asm("{ .reg .u64 t; cvta.to.shared.u64 t, %1; cvt.u32.u64 %0, t; }"
        : "=r"(a) : "l"(p));
    return a;
}
__device__ __forceinline__ void cpa16(uint32_t dst, const void* src) {
    asm volatile("cp.async.cg.shared.global [%0], [%1], 16;"
                 :: "r"(dst), "l"(src) : "memory");
}
#define CP_COMMIT() asm volatile("cp.async.commit_group;" ::: "memory")
#define CP_WAIT(n)  asm volatile("cp.async.wait_group %0;" :: "n"(n) : "memory")

__device__ __forceinline__ void ldsm4(uint32_t f[4], uint32_t addr) {
    asm volatile("ldmatrix.sync.aligned.m8n8.x4.shared.b16 {%0,%1,%2,%3}, [%4];"
                 : "=r"(f[0]), "=r"(f[1]), "=r"(f[2]), "=r"(f[3]) : "r"(addr));
}

__device__ __forceinline__ void mma_f16(float c[4], uint32_t a0, uint32_t a1,
                                        uint32_t a2, uint32_t a3,
                                        uint32_t b0, uint32_t b1) {
    asm volatile(
        "mma.sync.aligned.m16n8k16.row.col.f32.f16.f16.f32 "
        "{%0,%1,%2,%3}, {%4,%5,%6,%7}, {%8,%9}, {%0,%1,%2,%3};"
        : "+f"(c[0]), "+f"(c[1]), "+f"(c[2]), "+f"(c[3])
        : "r"(a0), "r"(a1), "r"(a2), "r"(a3), "r"(b0), "r"(b1));
}

// ---------------------------------------------------------------------------
// Prepass: fp32 -> fp16 for x and the four weights.
// ---------------------------------------------------------------------------
#define NX4 (MTOT*DM/4)
#define NW4 (DM*DM/4)
#define NCVT (NX4 + 4*NW4)

__global__ void __launch_bounds__(256) cvt16_kernel(
    const float* __restrict__ x, const float* __restrict__ wq,
    const float* __restrict__ wk, const float* __restrict__ wv,
    const float* __restrict__ wo)
{
    int i = blockIdx.x * 256 + threadIdx.x;
    if (i >= NCVT) return;
    const float4* src; __half* dst; int j;
    if (i < NX4)            { src = (const float4*)x;  dst = g_x16;  j = i; }
    else if (i < NX4+NW4)   { src = (const float4*)wq; dst = g_wq16; j = i - NX4; }
    else if (i < NX4+2*NW4) { src = (const float4*)wk; dst = g_wk16; j = i - NX4 - NW4; }
    else if (i < NX4+3*NW4) { src = (const float4*)wv; dst = g_wv16; j = i - NX4 - 2*NW4; }
    else                    { src = (const float4*)wo; dst = g_wo16; j = i - NX4 - 3*NW4; }
    float4 v = src[j];
    uint32_t* d = (uint32_t*)(dst + (size_t)j * 4);
    d[0] = pk(v.x, v.y);
    d[1] = pk(v.z, v.w);
}

// ---------------------------------------------------------------------------
// fp16 GEMM mainloop: C(128x128) = A @ W^T. BK=64, 3 smem stages, cp.async
// (2 groups in flight), ONE __syncthreads per chunk; 16 chunks total.
// Row stride 36 uint32 (32 data + 4 pad): ldsm 8-row starts hit banks 4r,
// conflict-free. Chunk ch issues ch+2 into stage (ch+2)%3 = stage drained
// before this chunk's barrier.
// ---------------------------------------------------------------------------
#define GST 36
#define GSTAGE (128 * GST)                 // units per matrix per stage
#define GEMM_SMEM (6 * GSTAGE * 4)         // 110592 B

__device__ __forceinline__ void gemm16_mainloop(
    const __half* __restrict__ A, const __half* __restrict__ W,
    int m0, int n0, uint32_t* gsm, float acc[4][4][4])
{
    const int tid = threadIdx.x, lane = tid & 31, wid = tid >> 5;
    const int wm = wid & 1, wn = wid >> 1;
    const int r = tid >> 1, h2 = tid & 1;

    const uint32_t sbase = smem_u32(gsm);
    const __half* ga = A + (size_t)(m0 + r) * 1024 + h2 * 32;
    const __half* gw = W + (size_t)(n0 + r) * 1024 + h2 * 32;
    const uint32_t du = (uint32_t)(r * GST + h2 * 16) * 4;

    const int arow = (lane & 7) + ((lane >> 3) & 1) * 8;
    const int acol = (lane >> 4) * 4;
    const int brow = (lane & 7) + ((lane >> 4) & 1) * 8;
    const int bcol = ((lane >> 3) & 1) * 4;
    const uint32_t aoff = (uint32_t)((wm * 64 + arow) * GST + acol) * 4;
    const uint32_t boff = (uint32_t)((wn * 32 + brow) * GST + bcol) * 4;
    const uint32_t wbase = sbase + 3 * GSTAGE * 4;

#pragma unroll
    for (int mi = 0; mi < 4; mi++)
#pragma unroll
        for (int nj = 0; nj < 4; nj++)
#pragma unroll
            for (int e = 0; e < 4; e++) acc[mi][nj][e] = 0.f;

    auto issue = [&](int ch, int st) {
        const uint32_t so = (uint32_t)st * (GSTAGE * 4);
        uint32_t da = sbase + so + du;
        uint32_t dw = wbase + so + du;
        const __half* a = ga + ch * 64;
        const __half* w = gw + ch * 64;
        cpa16(da, a);      cpa16(da + 16, a + 8);
        cpa16(da + 32, a + 16); cpa16(da + 48, a + 24);
        cpa16(dw, w);      cpa16(dw + 16, w + 8);
        cpa16(dw + 32, w + 16); cpa16(dw + 48, w + 24);
    };

    issue(0, 0); CP_COMMIT();
    issue(1, 1); CP_COMMIT();

    int st = 0;
    for (int ch = 0; ch < 16; ch++) {
        CP_WAIT(1);
        __syncthreads();
        const uint32_t so = (uint32_t)st * (GSTAGE * 4);
        const uint32_t aa = sbase + so + aoff;
        const uint32_t bb = wbase + so + boff;
#pragma unroll
        for (int kq = 0; kq < 4; kq++) {
            const uint32_t kk4 = (uint32_t)(kq * 8) * 4;
            uint32_t af[4][4], bq[2][4];
#pragma unroll
            for (int mi = 0; mi < 4; mi++)
                ldsm4(af[mi], aa + (uint32_t)(mi * 16 * GST) * 4 + kk4);
#pragma unroll
            for (int p = 0; p < 2; p++)
                ldsm4(bq[p], bb + (uint32_t)(p * 16 * GST) * 4 + kk4);
#pragma unroll
            for (int mi = 0; mi < 4; mi++)
#pragma unroll
                for (int p = 0; p < 2; p++) {
                    mma_f16(acc[mi][2*p],   af[mi][0], af[mi][1], af[mi][2], af[mi][3],
                            bq[p][0], bq[p][1]);
                    mma_f16(acc[mi][2*p+1], af[mi][0], af[mi][1], af[mi][2], af[mi][3],
                            bq[p][2], bq[p][3]);
                }
        }
        if (ch + 2 < 16) issue(ch + 2, (st + 2 >= 3) ? st - 1 : st + 2);
        CP_COMMIT();
        st = (st + 1 >= 3) ? 0 : st + 1;
    }
}

// ---------------------------------------------------------------------------
// Fused QKV projection. z: 0=Q (scaled), 1=K natural, 2=V transposed. fp16 out.
// ---------------------------------------------------------------------------
__global__ void __launch_bounds__(256) qkv_mma_kernel()
{
    extern __shared__ uint32_t gsm[];
    const int z = blockIdx.z;
    const __half* W = (z == 0) ? g_wq16 : (z == 1) ? g_wk16 : g_wv16;
    const int m0 = blockIdx.y * 128, n0 = blockIdx.x * 128;

    float acc[4][4][4];
    gemm16_mainloop(g_x16, W, m0, n0, gsm, acc);

    const int tid = threadIdx.x;
    const int lane = tid & 31, wid = tid >> 5;
    const int wm = wid & 1, wn = wid >> 1;
    const int g = lane >> 2, t = lane & 3;

#pragma unroll
    for (int mi = 0; mi < 4; mi++) {
#pragma unroll
        for (int half = 0; half < 2; half++) {
            const int m = m0 + wm * 64 + mi * 16 + g + half * 8;
            const int bb = m >> 11, tt = m & 2047;
#pragma unroll
            for (int nj = 0; nj < 4; nj++) {
                const int n = n0 + wn * 32 + nj * 8 + t * 2;
                const int h = n >> 6, d = n & 63;
                float v0 = acc[mi][nj][half * 2 + 0];
                float v1 = acc[mi][nj][half * 2 + 1];
                if (z == 0) {
                    *(uint32_t*)&g_Q16[((size_t)(bb * HN + h) * TSEQ + tt) * HDM + d] =
                        pk(v0 * 0.125f, v1 * 0.125f);
                } else if (z == 1) {
                    *(uint32_t*)&g_K16[((size_t)(bb * HN + h) * TSEQ + tt) * HDM + d] =
                        pk(v0, v1);
                } else {
                    g_Vt16[((size_t)(bb * HN + h) * HDM + d)     * TSEQ + tt] = __float2half(v0);
                    g_Vt16[((size_t)(bb * HN + h) * HDM + d + 1) * TSEQ + tt] = __float2half(v1);
                }
            }
        }
    }
}

// ---------------------------------------------------------------------------
// Output projection: d_out = g_O16 @ wo^T (fp32 out)
// ---------------------------------------------------------------------------
__global__ void __launch_bounds__(256) out_mma_kernel(float* __restrict__ out)
{
    extern __shared__ uint32_t gsm[];
    const int m0 = blockIdx.y * 128, n0 = blockIdx.x * 128;

    float acc[4][4][4];
    gemm16_mainloop(g_O16, g_wo16, m0, n0, gsm, acc);

    const int tid = threadIdx.x;
    const int lane = tid & 31, wid = tid >> 5;
    const int wm = wid & 1, wn = wid >> 1;
    const int g = lane >> 2, t = lane & 3;

#pragma unroll
    for (int mi = 0; mi < 4; mi++) {
#pragma unroll
        for (int half = 0; half < 2; half++) {
            const int m = m0 + wm * 64 + mi * 16 + g + half * 8;
#pragma unroll
            for (int nj = 0; nj < 4; nj++) {
                const int n = n0 + wn * 32 + nj * 8 + t * 2;
                float2 v = make_float2(acc[mi][nj][half * 2 + 0],
                                       acc[mi][nj][half * 2 + 1]);
                *(float2*)&out[(size_t)m * DM + n] = v;
            }
        }
    }
}

// ---------------------------------------------------------------------------
// Causal flash attention (unchanged from passing round 10 kernel).
// ---------------------------------------------------------------------------
#define FST 36
#define FLASH_SMEM ((128*FST + 3*64*FST*2 + 128*FST) * 4)   // 92160 B

__global__ void __launch_bounds__(256) flash_mma_kernel()
{
    extern __shared__ uint32_t fsu[];
    uint32_t* Ps = fsu + 128 * FST + 6 * 64 * FST;
    const uint32_t sbase = smem_u32(fsu);

    const int tid = threadIdx.x, lane = tid & 31, w = tid >> 5;
    const int g = lane >> 2, t = lane & 3;
    const int qt = gridDim.x - 1 - blockIdx.x;
    const int bh = blockIdx.y;
    const int q0 = qt * 128;
    const int rm = w * 16;

    const int arow = (lane & 7) + ((lane >> 3) & 1) * 8;
    const int acol = (lane >> 4) * 4;
    const int brow = (lane & 7) + ((lane >> 4) & 1) * 8;
    const int bcol = ((lane >> 3) & 1) * 4;
    const uint32_t qaddr = sbase + (uint32_t)((rm + arow) * FST + acol) * 4;
    const uint32_t paddr = qaddr + (uint32_t)(128 * FST + 6 * 64 * FST) * 4;
    const uint32_t kvoff = (uint32_t)(brow * FST + bcol) * 4;

    const __half* Qg = g_Q16  + (size_t)bh * TSEQ * HDM + (size_t)q0 * HDM;
    const __half* Kg = g_K16  + (size_t)bh * TSEQ * HDM;
    const __half* Vg = g_Vt16 + (size_t)bh * HDM * TSEQ;

#pragma unroll
    for (int i = 0; i < 4; i++) {
        int u = tid + i * 256, rq = u >> 3, c = u & 7;
        cpa16(sbase + (uint32_t)(rq * FST + c * 4) * 4, Qg + (size_t)rq * HDM + c * 8);
    }
    CP_COMMIT();

    auto issueKV = [&](int kt, int st) {
        const uint32_t ko = (uint32_t)(128 * FST + st * 64 * FST) * 4;
        const uint32_t vo = (uint32_t)(128 * FST + (3 + st) * 64 * FST) * 4;
#pragma unroll
        for (int i = 0; i < 2; i++) {
            int u = tid + i * 256, rk = u >> 3, c = u & 7;
            cpa16(sbase + ko + (uint32_t)(rk * FST + c * 4) * 4,
                  Kg + (size_t)(kt * 64 + rk) * HDM + c * 8);
            cpa16(sbase + vo + (uint32_t)(rk * FST + c * 4) * 4,
                  Vg + (size_t)rk * TSEQ + kt * 64 + c * 8);
        }
    };

    const int n_kt = 2 * (qt + 1);
    issueKV(0, 0); CP_COMMIT();
    issueKV(1, 1); CP_COMMIT();

    float mi[2] = {-INFINITY, -INFINITY}, li[2] = {0.f, 0.f};
    float accO[8][4];
#pragma unroll
    for (int nj = 0; nj < 8; nj++)
#pragma unroll
        for (int e = 0; e < 4; e++) accO[nj][e] = 0.f;

    int st = 0;
    for (int kt = 0; kt < n_kt; kt++) {
        CP_WAIT(1);
        __syncthreads();
        const uint32_t kbase = sbase + (uint32_t)(128 * FST + st * 64 * FST) * 4 + kvoff;
        const uint32_t vbase = sbase + (uint32_t)(128 * FST + (3 + st) * 64 * FST) * 4 + kvoff;

        float s[8][4];
#pragma unroll
        for (int nj = 0; nj < 8; nj++)
#pragma unroll
            for (int e = 0; e < 4; e++) s[nj][e] = 0.f;
#pragma unroll
        for (int ks = 0; ks < 4; ks++) {
            const uint32_t kk4 = (uint32_t)(ks * 8) * 4;
            uint32_t aq[4];
            ldsm4(aq, qaddr + kk4);
#pragma unroll
            for (int p = 0; p < 4; p++) {
                uint32_t bq[4];
                ldsm4(bq, kbase + (uint32_t)(p * 16 * FST) * 4 + kk4);
                mma_f16(s[2*p],   aq[0], aq[1], aq[2], aq[3], bq[0], bq[1]);
                mma_f16(s[2*p+1], aq[0], aq[1], aq[2], aq[3], bq[2], bq[3]);
            }
        }

        if (kt >= 2 * qt) {
            const int r0 = q0 + rm + g, r1 = r0 + 8;
#pragma unroll
            for (int nj = 0; nj < 8; nj++) {
                const int col = kt * 64 + nj * 8 + 2 * t;
                if (col     > r0) s[nj][0] = -INFINITY;
                if (col + 1 > r0) s[nj][1] = -INFINITY;
                if (col     > r1) s[nj][2] = -INFINITY;
                if (col + 1 > r1) s[nj][3] = -INFINITY;
            }
        }

#pragma unroll
        for (int h = 0; h < 2; h++) {
            float vm = -INFINITY;
#pragma unroll
            for (int nj = 0; nj < 8; nj++)
                vm = fmaxf(vm, fmaxf(s[nj][2 * h], s[nj][2 * h + 1]));
            vm = fmaxf(vm, __shfl_xor_sync(0xffffffffu, vm, 1));
            vm = fmaxf(vm, __shfl_xor_sync(0xffffffffu, vm, 2));
            const float mnew = fmaxf(mi[h], vm);
            const float alpha = __expf(mi[h] - mnew);
            float rs = 0.f;
            const int prow = (rm + g + 8 * h) * FST;
#pragma unroll
            for (int nj = 0; nj < 8; nj++) {
                float p0 = __expf(s[nj][2 * h]     - mnew);
                float p1 = __expf(s[nj][2 * h + 1] - mnew);
                rs += p0 + p1;
                Ps[prow + nj * 4 + t] = pk(p0, p1);
            }
            rs += __shfl_xor_sync(0xffffffffu, rs, 1);
            rs += __shfl_xor_sync(0xffffffffu, rs, 2);
            li[h] = li[h] * alpha + rs;
            mi[h] = mnew;
#pragma unroll
            for (int nj = 0; nj < 8; nj++) {
                accO[nj][2 * h]     *= alpha;
                accO[nj][2 * h + 1] *= alpha;
            }
        }
        __syncwarp();

#pragma unroll
        for (int ks = 0; ks < 4; ks++) {
            const uint32_t kk4 = (uint32_t)(ks * 8) * 4;
            uint32_t ap[4];
            ldsm4(ap, paddr + kk4);
#pragma unroll
            for (int p = 0; p < 4; p++) {
                uint32_t bq[4];
                ldsm4(bq, vbase + (uint32_t)(p * 16 * FST) * 4 + kk4);
                mma_f16(accO[2*p],   ap[0], ap[1], ap[2], ap[3], bq[0], bq[1]);
                mma_f16(accO[2*p+1], ap[0], ap[1], ap[2], ap[3], bq[2], bq[3]);
            }
        }

        if (kt + 2 < n_kt) issueKV(kt + 2, (st + 2 >= 3) ? st - 1 : st + 2);
        CP_COMMIT();
        st = (st + 1 >= 3) ? 0 : st + 1;
    }

    const int b = bh >> 4, hh = bh & 15;
    const float inv0 = 1.f / li[0], inv1 = 1.f / li[1];
    const int r0 = q0 + rm + g;
#pragma unroll
    for (int nj = 0; nj < 8; nj++) {
        const int col = hh * 64 + nj * 8 + 2 * t;
        *(uint32_t*)&g_O16[(size_t)(b * TSEQ + r0) * DM + col] =
            pk(accO[nj][0] * inv0, accO[nj][1] * inv0);
        *(uint32_t*)&g_O16[(size_t)(b * TSEQ + r0 + 8) * DM + col] =
            pk(accO[nj][2] * inv1, accO[nj][3] * inv1);
    }
}

// ---------------------------------------------------------------------------
extern "C" void kernel_launch(void* const* d_in, const int* in_sizes, int n_in,
                              void* d_out, int out_size)
{
    const float* x  = (const float*)d_in[0];
    const float* wq = (const float*)d_in[1];
    const float* wk = (const float*)d_in[2];
    const float* wv = (const float*)d_in[3];
    const float* wo = (const float*)d_in[4];

    cudaFuncSetAttribute(qkv_mma_kernel, cudaFuncAttributeMaxDynamicSharedMemorySize, GEMM_SMEM);
    cudaFuncSetAttribute(out_mma_kernel, cudaFuncAttributeMaxDynamicSharedMemorySize, GEMM_SMEM);
    cudaFuncSetAttribute(flash_mma_kernel, cudaFuncAttributeMaxDynamicSharedMemorySize, FLASH_SMEM);

    cvt16_kernel<<<(NCVT + 255) / 256, 256>>>(x, wq, wk, wv, wo);
    qkv_mma_kernel<<<dim3(DM / 128, MTOT / 128, 3), 256, GEMM_SMEM>>>();
    flash_mma_kernel<<<dim3(TSEQ / 128, BSZ * HN), 256, FLASH_SMEM>>>();
    out_mma_kernel<<<dim3(DM / 128, MTOT / 128), 256, GEMM_SMEM>>>((float*)d_out);
}

// round 12
// speedup vs baseline: 1.1223x; 1.1223x over previous
#include <cuda_runtime.h>
#include <cuda_fp16.h>
#include <math.h>
#include <cstdint>

// Problem constants
#define BSZ 2
#define TSEQ 2048
#define DM   1024
#define HN   16
#define HDM  64
#define MTOT (BSZ*TSEQ)   // 4096

// Scratch (allocation-free rule: __device__ globals)
__device__ __half g_x16 [MTOT*DM];
__device__ __half g_wq16[DM*DM];
__device__ __half g_wk16[DM*DM];
__device__ __half g_wv16[DM*DM];
__device__ __half g_wo16[DM*DM];
__device__ __half g_Q16 [BSZ*HN*TSEQ*HDM];  // [B,H,T,hd], pre-scaled 1/8
__device__ __half g_K16 [BSZ*HN*TSEQ*HDM];  // [B,H,T,hd]
__device__ __half g_Vt16[BSZ*HN*HDM*TSEQ];  // [B,H,hd,T]
__device__ __half g_O16 [MTOT*DM];          // [B*T, D]

// ---------------------------------------------------------------------------
// helpers
// ---------------------------------------------------------------------------
__device__ __forceinline__ uint32_t pk(float lo, float hi) {
    __half2 h = __floats2half2_rn(lo, hi);
    return *(uint32_t*)&h;
}
__device__ __forceinline__ uint32_t smem_u32(const void* p) {
    uint32_t a;
    asm("{ .reg .u64 t; cvta.to.shared.u64 t, %1; cvt.u32.u64 %0, t; }"
        : "=r"(a) : "l"(p));
    return a;
}
__device__ __forceinline__ void cpa16(uint32_t dst, const void* src) {
    asm volatile("cp.async.cg.shared.global [%0], [%1], 16;"
                 :: "r"(dst), "l"(src) : "memory");
}
#define CP_COMMIT() asm volatile("cp.async.commit_group;" ::: "memory")
#define CP_WAIT(n)  asm volatile("cp.async.wait_group %0;" :: "n"(n) : "memory")

__device__ __forceinline__ void ldsm4(uint32_t f[4], uint32_t addr) {
    asm volatile("ldmatrix.sync.aligned.m8n8.x4.shared.b16 {%0,%1,%2,%3}, [%4];"
                 : "=r"(f[0]), "=r"(f[1]), "=r"(f[2]), "=r"(f[3]) : "r"(addr));
}

__device__ __forceinline__ void mma_f16(float c[4], uint32_t a0, uint32_t a1,
                                        uint32_t a2, uint32_t a3,
                                        uint32_t b0, uint32_t b1) {
    asm volatile(
        "mma.sync.aligned.m16n8k16.row.col.f32.f16.f16.f32 "
        "{%0,%1,%2,%3}, {%4,%5,%6,%7}, {%8,%9}, {%0,%1,%2,%3};"
        : "+f"(c[0]), "+f"(c[1]), "+f"(c[2]), "+f"(c[3])
        : "r"(a0), "r"(a1), "r"(a2), "r"(a3), "r"(b0), "r"(b1));
}

// ---------------------------------------------------------------------------
// Prepass: fp32 -> fp16 for x and the four weights.
// ---------------------------------------------------------------------------
#define NX4 (MTOT*DM/4)
#define NW4 (DM*DM/4)
#define NCVT (NX4 + 4*NW4)

__global__ void __launch_bounds__(256) cvt16_kernel(
    const float* __restrict__ x, const float* __restrict__ wq,
    const float* __restrict__ wk, const float* __restrict__ wv,
    const float* __restrict__ wo)
{
    int i = blockIdx.x * 256 + threadIdx.x;
    if (i >= NCVT) return;
    const float4* src; __half* dst; int j;
    if (i < NX4)            { src = (const float4*)x;  dst = g_x16;  j = i; }
    else if (i < NX4+NW4)   { src = (const float4*)wq; dst = g_wq16; j = i - NX4; }
    else if (i < NX4+2*NW4) { src = (const float4*)wk; dst = g_wk16; j = i - NX4 - NW4; }
    else if (i < NX4+3*NW4) { src = (const float4*)wv; dst = g_wv16; j = i - NX4 - 2*NW4; }
    else                    { src = (const float4*)wo; dst = g_wo16; j = i - NX4 - 3*NW4; }
    float4 v = src[j];
    uint32_t* d = (uint32_t*)(dst + (size_t)j * 4);
    d[0] = pk(v.x, v.y);
    d[1] = pk(v.z, v.w);
}

// ---------------------------------------------------------------------------
// fp16 GEMM mainloop (R10-proven shape): C(128x128) = A @ W^T. BK=32,
// 4 smem stages, 3 cp.async groups in flight, ONE __syncthreads per chunk.
// CHANGE vs R10: next chunk's cp.async is issued immediately AFTER the
// barrier (before the MMA burst) — the written stage (ch+3)%4 was drained
// at chunk ch-1 and all warps are past this chunk's barrier, so it's the
// same epoch as before, just ~300 cycles earlier in flight.
// Row stride 20 uint32: ldsm 8-row starts hit banks {0,20,8,28,16,4,24,12}.
// ---------------------------------------------------------------------------
#define GST 20
#define GEMM_SMEM (8 * 128 * GST * 4)   // 81920 B

__device__ __forceinline__ void gemm16_mainloop(
    const __half* __restrict__ A, const __half* __restrict__ W,
    int m0, int n0, uint32_t* gsm, float acc[4][4][4])
{
    const int tid = threadIdx.x, lane = tid & 31, wid = tid >> 5;
    const int wm = wid & 1, wn = wid >> 1;
    const int r = tid >> 1, h2 = tid & 1;

    const uint32_t sbase = smem_u32(gsm);
    const __half* ga = A + (size_t)(m0 + r) * 1024 + h2 * 16;
    const __half* gw = W + (size_t)(n0 + r) * 1024 + h2 * 16;
    const uint32_t du = (uint32_t)(r * GST + h2 * 8) * 4;

    const int arow = (lane & 7) + ((lane >> 3) & 1) * 8;
    const int acol = (lane >> 4) * 4;
    const int brow = (lane & 7) + ((lane >> 4) & 1) * 8;
    const int bcol = ((lane >> 3) & 1) * 4;
    const uint32_t aoff = (uint32_t)((wm * 64 + arow) * GST + acol) * 4;
    const uint32_t boff = (uint32_t)((wn * 32 + brow) * GST + bcol) * 4;
    const uint32_t wbase = sbase + 4 * 128 * GST * 4;

#pragma unroll
    for (int mi = 0; mi < 4; mi++)
#pragma unroll
        for (int nj = 0; nj < 4; nj++)
#pragma unroll
            for (int e = 0; e < 4; e++) acc[mi][nj][e] = 0.f;

    auto issue = [&](int ch, int st) {
        const uint32_t so = (uint32_t)st * (128 * GST * 4);
        uint32_t da = sbase + so + du;
        uint32_t dw = wbase + so + du;
        const __half* a = ga + ch * 32;
        const __half* w = gw + ch * 32;
        cpa16(da, a);      cpa16(da + 16, a + 8);
        cpa16(dw, w);      cpa16(dw + 16, w + 8);
    };

    issue(0, 0); CP_COMMIT();
    issue(1, 1); CP_COMMIT();
    issue(2, 2); CP_COMMIT();

    for (int ch = 0; ch < 32; ch++) {
        const int st = ch & 3;
        CP_WAIT(2);
        __syncthreads();
        // EARLY ISSUE: start next chunk's copies before the MMA burst.
        if (ch + 3 < 32) issue(ch + 3, (ch + 3) & 3);
        CP_COMMIT();
        const uint32_t so = (uint32_t)st * (128 * GST * 4);
        const uint32_t aa = sbase + so + aoff;
        const uint32_t bb = wbase + so + boff;
#pragma unroll
        for (int kq = 0; kq < 2; kq++) {
            const uint32_t kk4 = (uint32_t)(kq * 8) * 4;
            uint32_t af[4][4], bq[2][4];
#pragma unroll
            for (int mi = 0; mi < 4; mi++)
                ldsm4(af[mi], aa + (uint32_t)(mi * 16 * GST) * 4 + kk4);
#pragma unroll
            for (int p = 0; p < 2; p++)
                ldsm4(bq[p], bb + (uint32_t)(p * 16 * GST) * 4 + kk4);
#pragma unroll
            for (int mi = 0; mi < 4; mi++)
#pragma unroll
                for (int p = 0; p < 2; p++) {
                    mma_f16(acc[mi][2*p],   af[mi][0], af[mi][1], af[mi][2], af[mi][3],
                            bq[p][0], bq[p][1]);
                    mma_f16(acc[mi][2*p+1], af[mi][0], af[mi][1], af[mi][2], af[mi][3],
                            bq[p][2], bq[p][3]);
                }
        }
    }
}

// ---------------------------------------------------------------------------
// Fused QKV projection. z: 0=Q (scaled), 1=K natural, 2=V transposed. fp16 out.
// ---------------------------------------------------------------------------
__global__ void __launch_bounds__(256) qkv_mma_kernel()
{
    extern __shared__ uint32_t gsm[];
    const int z = blockIdx.z;
    const __half* W = (z == 0) ? g_wq16 : (z == 1) ? g_wk16 : g_wv16;
    const int m0 = blockIdx.y * 128, n0 = blockIdx.x * 128;

    float acc[4][4][4];
    gemm16_mainloop(g_x16, W, m0, n0, gsm, acc);

    const int tid = threadIdx.x;
    const int lane = tid & 31, wid = tid >> 5;
    const int wm = wid & 1, wn = wid >> 1;
    const int g = lane >> 2, t = lane & 3;

#pragma unroll
    for (int mi = 0; mi < 4; mi++) {
#pragma unroll
        for (int half = 0; half < 2; half++) {
            const int m = m0 + wm * 64 + mi * 16 + g + half * 8;
            const int bb = m >> 11, tt = m & 2047;
#pragma unroll
            for (int nj = 0; nj < 4; nj++) {
                const int n = n0 + wn * 32 + nj * 8 + t * 2;
                const int h = n >> 6, d = n & 63;
                float v0 = acc[mi][nj][half * 2 + 0];
                float v1 = acc[mi][nj][half * 2 + 1];
                if (z == 0) {
                    *(uint32_t*)&g_Q16[((size_t)(bb * HN + h) * TSEQ + tt) * HDM + d] =
                        pk(v0 * 0.125f, v1 * 0.125f);
                } else if (z == 1) {
                    *(uint32_t*)&g_K16[((size_t)(bb * HN + h) * TSEQ + tt) * HDM + d] =
                        pk(v0, v1);
                } else {
                    g_Vt16[((size_t)(bb * HN + h) * HDM + d)     * TSEQ + tt] = __float2half(v0);
                    g_Vt16[((size_t)(bb * HN + h) * HDM + d + 1) * TSEQ + tt] = __float2half(v1);
                }
            }
        }
    }
}

// ---------------------------------------------------------------------------
// Output projection: d_out = g_O16 @ wo^T (fp32 out)
// ---------------------------------------------------------------------------
__global__ void __launch_bounds__(256) out_mma_kernel(float* __restrict__ out)
{
    extern __shared__ uint32_t gsm[];
    const int m0 = blockIdx.y * 128, n0 = blockIdx.x * 128;

    float acc[4][4][4];
    gemm16_mainloop(g_O16, g_wo16, m0, n0, gsm, acc);

    const int tid = threadIdx.x;
    const int lane = tid & 31, wid = tid >> 5;
    const int wm = wid & 1, wn = wid >> 1;
    const int g = lane >> 2, t = lane & 3;

#pragma unroll
    for (int mi = 0; mi < 4; mi++) {
#pragma unroll
        for (int half = 0; half < 2; half++) {
            const int m = m0 + wm * 64 + mi * 16 + g + half * 8;
#pragma unroll
            for (int nj = 0; nj < 4; nj++) {
                const int n = n0 + wn * 32 + nj * 8 + t * 2;
                float2 v = make_float2(acc[mi][nj][half * 2 + 0],
                                       acc[mi][nj][half * 2 + 1]);
                *(float2*)&out[(size_t)m * DM + n] = v;
            }
        }
    }
}

// ---------------------------------------------------------------------------
// Causal flash attention (R10-proven), with the same early-issue reorder:
// issueKV for kt+2 fires right after this iteration's barrier.
// ---------------------------------------------------------------------------
#define FST 36
#define FLASH_SMEM ((128*FST + 3*64*FST*2 + 128*FST) * 4)   // 92160 B

__global__ void __launch_bounds__(256) flash_mma_kernel()
{
    extern __shared__ uint32_t fsu[];
    uint32_t* Ps = fsu + 128 * FST + 6 * 64 * FST;
    const uint32_t sbase = smem_u32(fsu);

    const int tid = threadIdx.x, lane = tid & 31, w = tid >> 5;
    const int g = lane >> 2, t = lane & 3;
    const int qt = gridDim.x - 1 - blockIdx.x;
    const int bh = blockIdx.y;
    const int q0 = qt * 128;
    const int rm = w * 16;

    const int arow = (lane & 7) + ((lane >> 3) & 1) * 8;
    const int acol = (lane >> 4) * 4;
    const int brow = (lane & 7) + ((lane >> 4) & 1) * 8;
    const int bcol = ((lane >> 3) & 1) * 4;
    const uint32_t qaddr = sbase + (uint32_t)((rm + arow) * FST + acol) * 4;
    const uint32_t paddr = qaddr + (uint32_t)(128 * FST + 6 * 64 * FST) * 4;
    const uint32_t kvoff = (uint32_t)(brow * FST + bcol) * 4;

    const __half* Qg = g_Q16  + (size_t)bh * TSEQ * HDM + (size_t)q0 * HDM;
    const __half* Kg = g_K16  + (size_t)bh * TSEQ * HDM;
    const __half* Vg = g_Vt16 + (size_t)bh * HDM * TSEQ;

#pragma unroll
    for (int i = 0; i < 4; i++) {
        int u = tid + i * 256, rq = u >> 3, c = u & 7;
        cpa16(sbase + (uint32_t)(rq * FST + c * 4) * 4, Qg + (size_t)rq * HDM + c * 8);
    }
    CP_COMMIT();

    auto issueKV = [&](int kt, int st) {
        const uint32_t ko = (uint32_t)(128 * FST + st * 64 * FST) * 4;
        const uint32_t vo = (uint32_t)(128 * FST + (3 + st) * 64 * FST) * 4;
#pragma unroll
        for (int i = 0; i < 2; i++) {
            int u = tid + i * 256, rk = u >> 3, c = u & 7;
            cpa16(sbase + ko + (uint32_t)(rk * FST + c * 4) * 4,
                  Kg + (size_t)(kt * 64 + rk) * HDM + c * 8);
            cpa16(sbase + vo + (uint32_t)(rk * FST + c * 4) * 4,
                  Vg + (size_t)rk * TSEQ + kt * 64 + c * 8);
        }
    };

    const int n_kt = 2 * (qt + 1);
    issueKV(0, 0); CP_COMMIT();
    issueKV(1, 1); CP_COMMIT();

    float mi[2] = {-INFINITY, -INFINITY}, li[2] = {0.f, 0.f};
    float accO[8][4];
#pragma unroll
    for (int nj = 0; nj < 8; nj++)
#pragma unroll
        for (int e = 0; e < 4; e++) accO[nj][e] = 0.f;

    int st = 0;
    for (int kt = 0; kt < n_kt; kt++) {
        CP_WAIT(1);
        __syncthreads();
        // EARLY ISSUE: stage (st+2)%3 was drained at kt-1; all warps are past
        // this iteration's barrier, so writing it now is safe.
        if (kt + 2 < n_kt) issueKV(kt + 2, (st + 2 >= 3) ? st - 1 : st + 2);
        CP_COMMIT();
        const uint32_t kbase = sbase + (uint32_t)(128 * FST + st * 64 * FST) * 4 + kvoff;
        const uint32_t vbase = sbase + (uint32_t)(128 * FST + (3 + st) * 64 * FST) * 4 + kvoff;

        float s[8][4];
#pragma unroll
        for (int nj = 0; nj < 8; nj++)
#pragma unroll
            for (int e = 0; e < 4; e++) s[nj][e] = 0.f;
#pragma unroll
        for (int ks = 0; ks < 4; ks++) {
            const uint32_t kk4 = (uint32_t)(ks * 8) * 4;
            uint32_t aq[4];
            ldsm4(aq, qaddr + kk4);
#pragma unroll
            for (int p = 0; p < 4; p++) {
                uint32_t bq[4];
                ldsm4(bq, kbase + (uint32_t)(p * 16 * FST) * 4 + kk4);
                mma_f16(s[2*p],   aq[0], aq[1], aq[2], aq[3], bq[0], bq[1]);
                mma_f16(s[2*p+1], aq[0], aq[1], aq[2], aq[3], bq[2], bq[3]);
            }
        }

        if (kt >= 2 * qt) {
            const int r0 = q0 + rm + g, r1 = r0 + 8;
#pragma unroll
            for (int nj = 0; nj < 8; nj++) {
                const int col = kt * 64 + nj * 8 + 2 * t;
                if (col     > r0) s[nj][0] = -INFINITY;
                if (col + 1 > r0) s[nj][1] = -INFINITY;
                if (col     > r1) s[nj][2] = -INFINITY;
                if (col + 1 > r1) s[nj][3] = -INFINITY;
            }
        }

#pragma unroll
        for (int h = 0; h < 2; h++) {
            float vm = -INFINITY;
#pragma unroll
            for (int nj = 0; nj < 8; nj++)
                vm = fmaxf(vm, fmaxf(s[nj][2 * h], s[nj][2 * h + 1]));
            vm = fmaxf(vm, __shfl_xor_sync(0xffffffffu, vm, 1));
            vm = fmaxf(vm, __shfl_xor_sync(0xffffffffu, vm, 2));
            const float mnew = fmaxf(mi[h], vm);
            const float alpha = __expf(mi[h] - mnew);
            float rs = 0.f;
            const int prow = (rm + g + 8 * h) * FST;
#pragma unroll
            for (int nj = 0; nj < 8; nj++) {
                float p0 = __expf(s[nj][2 * h]     - mnew);
                float p1 = __expf(s[nj][2 * h + 1] - mnew);
                rs += p0 + p1;
                Ps[prow + nj * 4 + t] = pk(p0, p1);
            }
            rs += __shfl_xor_sync(0xffffffffu, rs, 1);
            rs += __shfl_xor_sync(0xffffffffu, rs, 2);
            li[h] = li[h] * alpha + rs;
            mi[h] = mnew;
#pragma unroll
            for (int nj = 0; nj < 8; nj++) {
                accO[nj][2 * h]     *= alpha;
                accO[nj][2 * h + 1] *= alpha;
            }
        }
        __syncwarp();

#pragma unroll
        for (int ks = 0; ks < 4; ks++) {
            const uint32_t kk4 = (uint32_t)(ks * 8) * 4;
            uint32_t ap[4];
            ldsm4(ap, paddr + kk4);
#pragma unroll
            for (int p = 0; p < 4; p++) {
                uint32_t bq[4];
                ldsm4(bq, vbase + (uint32_t)(p * 16 * FST) * 4 + kk4);
                mma_f16(accO[2*p],   ap[0], ap[1], ap[2], ap[3], bq[0], bq[1]);
                mma_f16(accO[2*p+1], ap[0], ap[1], ap[2], ap[3], bq[2], bq[3]);
            }
        }

        st = (st + 1 >= 3) ? 0 : st + 1;
    }

    const int b = bh >> 4, hh = bh & 15;
    const float inv0 = 1.f / li[0], inv1 = 1.f / li[1];
    const int r0 = q0 + rm + g;
#pragma unroll
    for (int nj = 0; nj < 8; nj++) {
        const int col = hh * 64 + nj * 8 + 2 * t;
        *(uint32_t*)&g_O16[(size_t)(b * TSEQ + r0) * DM + col] =
            pk(accO[nj][0] * inv0, accO[nj][1] * inv0);
        *(uint32_t*)&g_O16[(size_t)(b * TSEQ + r0 + 8) * DM + col] =
            pk(accO[nj][2] * inv1, accO[nj][3] * inv1);
    }
}

// ---------------------------------------------------------------------------
extern "C" void kernel_launch(void* const* d_in, const int* in_sizes, int n_in,
                              void* d_out, int out_size)
{
    const float* x  = (const float*)d_in[0];
    const float* wq = (const float*)d_in[1];
    const float* wk = (const float*)d_in[2];
    const float* wv = (const float*)d_in[3];
    const float* wo = (const float*)d_in[4];

    cudaFuncSetAttribute(qkv_mma_kernel, cudaFuncAttributeMaxDynamicSharedMemorySize, GEMM_SMEM);
    cudaFuncSetAttribute(out_mma_kernel, cudaFuncAttributeMaxDynamicSharedMemorySize, GEMM_SMEM);
    cudaFuncSetAttribute(flash_mma_kernel, cudaFuncAttributeMaxDynamicSharedMemorySize, FLASH_SMEM);

    cvt16_kernel<<<(NCVT + 255) / 256, 256>>>(x, wq, wk, wv, wo);
    qkv_mma_kernel<<<dim3(DM / 128, MTOT / 128, 3), 256, GEMM_SMEM>>>();
    flash_mma_kernel<<<dim3(TSEQ / 128, BSZ * HN), 256, FLASH_SMEM>>>();
    out_mma_kernel<<<dim3(DM / 128, MTOT / 128), 256, GEMM_SMEM>>>((float*)d_out);
}